// round 11
// baseline (speedup 1.0000x reference)
#include <cuda_runtime.h>
#include <cuda_fp16.h>
#include <cstdint>

#define D_MODEL    2048
#define D_HIDDEN   2048
#define NUM_EXPERTS  16
#define N_TOKENS   8192

// mma.sync GEMM tile
#define BM 128
#define BN 128
#define BK 64
#define KCHUNKS (D_MODEL / BK)      // 32
#define NTILES  (D_HIDDEN / BN)     // 16
#define NSTAGES 3

// ---------------- device scratch (no allocations allowed) ----------------
__device__ int   g_counts[2][NUM_EXPERTS];
__device__ int   g_bucket[2][NUM_EXPERTS][N_TOKENS];
__device__ float g_gate  [2][NUM_EXPERTS][N_TOKENS];

__device__ __half g_xf[(size_t)N_TOKENS * D_MODEL];              // x -> fp16
// W transposed to [e][n][k] (K contiguous), rounded to fp16
__device__ __half g_wf[(size_t)NUM_EXPERTS * D_HIDDEN * D_MODEL];

// ---------------- PTX helpers (compute_103-safe: no tcgen05) ----------------
__device__ __forceinline__ uint32_t smem_u32(const void* p) {
    uint32_t a;
    asm("{ .reg .u64 t; cvta.to.shared.u64 t, %1; cvt.u32.u64 %0, t; }"
        : "=r"(a) : "l"(p));
    return a;
}
__device__ __forceinline__ void cp16(uint32_t dst, const void* src) {
    asm volatile("cp.async.cg.shared.global [%0], [%1], 16;\n"
                 :: "r"(dst), "l"(src));
}
#define CP_COMMIT() asm volatile("cp.async.commit_group;" ::: "memory")
#define CP_WAIT1()  asm volatile("cp.async.wait_group 1;" ::: "memory")

__device__ __forceinline__ void ldsm4(uint32_t* r, uint32_t addr) {
    asm volatile("ldmatrix.sync.aligned.m8n8.x4.shared.b16 {%0,%1,%2,%3}, [%4];"
                 : "=r"(r[0]), "=r"(r[1]), "=r"(r[2]), "=r"(r[3]) : "r"(addr));
}
__device__ __forceinline__ void mma_fp16(float* d, const uint32_t* a,
                                         uint32_t b0, uint32_t b1) {
    asm volatile(
        "mma.sync.aligned.m16n8k16.row.col.f32.f16.f16.f32 "
        "{%0,%1,%2,%3}, {%4,%5,%6,%7}, {%8,%9}, {%0,%1,%2,%3};"
        : "+f"(d[0]), "+f"(d[1]), "+f"(d[2]), "+f"(d[3])
        : "r"(a[0]), "r"(a[1]), "r"(a[2]), "r"(a[3]), "r"(b0), "r"(b1));
}

// ---------------- small kernels ----------------
__global__ void reset_kernel() {
    if (threadIdx.x < 2 * NUM_EXPERTS)
        ((int*)g_counts)[threadIdx.x] = 0;
}

__global__ void router_kernel(const float* __restrict__ x,
                              const float* __restrict__ rw) {
    __shared__ float sx[D_MODEL];
    __shared__ float slog[NUM_EXPERTS];
    const int token = blockIdx.x;
    const int tid   = threadIdx.x;   // 128
    const float4* xr = (const float4*)(x + (size_t)token * D_MODEL);
    for (int i = tid; i < D_MODEL / 4; i += 128)
        ((float4*)sx)[i] = xr[i];
    __syncthreads();

    const int warp = tid >> 5, lane = tid & 31;
    for (int e = warp; e < NUM_EXPERTS; e += 4) {
        const float* w = rw + (size_t)e * D_MODEL;
        float s = 0.f;
#pragma unroll 8
        for (int i = lane; i < D_MODEL; i += 32)
            s += sx[i] * __ldg(w + i);
#pragma unroll
        for (int o = 16; o > 0; o >>= 1)
            s += __shfl_xor_sync(0xffffffffu, s, o);
        if (lane == 0) slog[e] = s;
    }
    __syncthreads();

    if (tid == 0) {
        float l0 = -3.4e38f, l1 = -3.4e38f;
        int e0 = 0, e1 = 0;
#pragma unroll
        for (int e = 0; e < NUM_EXPERTS; e++) {
            float v = slog[e];
            if (v > l0)      { l1 = l0; e1 = e0; l0 = v; e0 = e; }
            else if (v > l1) { l1 = v;  e1 = e; }
        }
        float g0 = 1.f / (1.f + expf(l1 - l0));
        float g1 = 1.f - g0;
        int p0 = atomicAdd(&g_counts[0][e0], 1);
        g_bucket[0][e0][p0] = token;
        g_gate  [0][e0][p0] = g0;
        int p1 = atomicAdd(&g_counts[1][e1], 1);
        g_bucket[1][e1][p1] = token;
        g_gate  [1][e1][p1] = g1;
    }
}

// fp32 -> fp16 round of x (K-major)
__global__ void convert_x_kernel(const float* __restrict__ x) {
    size_t i = (size_t)blockIdx.x * blockDim.x + threadIdx.x;  // one float4
    float4 v = ((const float4*)x)[i];
    __half2* d = (__half2*)g_xf;
    d[2 * i]     = __floats2half2_rn(v.x, v.y);
    d[2 * i + 1] = __floats2half2_rn(v.z, v.w);
}

// W [e][k][n] fp32  ->  transposed fp16 [e][n][k]
__global__ void convert_w_kernel(const float* __restrict__ W) {
    __shared__ float t[32][33];
    const int e  = blockIdx.z;
    const int k0 = blockIdx.y * 32;
    const int n0 = blockIdx.x * 32;
    const int tid = threadIdx.x;        // 256
    const float* src = W + (size_t)e * D_MODEL * D_HIDDEN;

    // load 32x32 fp32 tile: one float4 per thread
    {
        const int r  = tid >> 3;        // 0..31 (k)
        const int c4 = tid & 7;         // 0..7  (n group of 4)
        float4 v = *(const float4*)&src[(size_t)(k0 + r) * D_HIDDEN + n0 + c4 * 4];
        t[r][c4 * 4 + 0] = v.x;
        t[r][c4 * 4 + 1] = v.y;
        t[r][c4 * 4 + 2] = v.z;
        t[r][c4 * 4 + 3] = v.w;
    }
    __syncthreads();

    // write: thread handles (n, 4 consecutive k) -> one 8B packed store
    {
        const int n  = tid >> 3;        // 0..31
        const int kg = tid & 7;         // 0..7 -> k = kg*4..+3
        float f[4];
#pragma unroll
        for (int j = 0; j < 4; j++) f[j] = t[kg * 4 + j][n];
        __half2 p0 = __floats2half2_rn(f[0], f[1]);
        __half2 p1 = __floats2half2_rn(f[2], f[3]);
        size_t idx = ((size_t)e * D_HIDDEN + n0 + n) * D_MODEL + k0 + kg * 4;
        *(__half2*)&g_wf[idx]     = p0;
        *(__half2*)&g_wf[idx + 2] = p1;
    }
}

// ---------------- mma.sync gathered GEMM (fp16, BK=64, 3-stage pipe) --------
// smem: [0:512) rows_s | [512:1024) gates_s | [1024:) 3 stages x 32KB
//   stage: A 16K | B 16K   (tiles 128 rows x 64 fp16,
//   row = 128B = 8 x 16B chunks, chunk swizzle c' = c ^ (row & 7))
#define STAGE_B  32768
#define SMEM_DYN (1024 + NSTAGES * STAGE_B)

template <int SLOT>
__global__ void __launch_bounds__(256, 2)
moe_gemm_mma(float* __restrict__ out) {
    const int e    = blockIdx.z;
    const int cnt  = g_counts[SLOT][e];
    const int row0 = blockIdx.y * BM;
    if (row0 >= cnt) return;
    const int n0  = blockIdx.x * BN;
    const int tid = threadIdx.x;

    extern __shared__ char smem[];
    int*   rows_s  = (int*)smem;
    float* gates_s = (float*)(smem + 512);
    const uint32_t sb    = smem_u32(smem);
    const uint32_t tiles = sb + 1024;

    if (tid < BM) {
        int idx = row0 + tid;
        if (idx < cnt) {
            rows_s[tid]  = g_bucket[SLOT][e][idx];
            gates_s[tid] = g_gate[SLOT][e][idx];
        } else {
            rows_s[tid]  = g_bucket[SLOT][e][row0];
            gates_s[tid] = 0.f;
        }
    }
    __syncthreads();

    const size_t wbase = ((size_t)e * D_HIDDEN + n0) * D_MODEL;

    // stage loader: A+B = 2 x 1024 16B chunks, 4+4 per thread
    auto load_stage = [&](int i) {
        const int kof = i * BK;
        const uint32_t st = tiles + (i % NSTAGES) * STAGE_B;
#pragma unroll
        for (int q = 0; q < 4; q++) {
            const int ch = tid * 4 + q;
            const int r = ch >> 3, c = ch & 7;
            const uint32_t d = r * 128 + ((c ^ (r & 7)) << 4);
            const size_t asrc = (size_t)rows_s[r] * D_MODEL + kof + c * 8;
            cp16(st + d, g_xf + asrc);
            const size_t bsrc = wbase + (size_t)r * D_MODEL + kof + c * 8;
            cp16(st + 16384 + d, g_wf + bsrc);
        }
        CP_COMMIT();
    };

    // warp layout: 4 (M) x 2 (N); warp tile 32x64
    const int wid = tid >> 5, lane = tid & 31;
    const int wm = wid & 3, wn = wid >> 2;

    // per-lane ldmatrix address components
    uint32_t a_row[2], a_sw[2];
#pragma unroll
    for (int mt = 0; mt < 2; mt++) {
        const int m = wm * 32 + mt * 16 + ((lane >> 3) & 1) * 8 + (lane & 7);
        a_row[mt] = m * 128;
        a_sw[mt]  = m & 7;
    }
    const uint32_t a_hc = lane >> 4;
    uint32_t b_row[4], b_sw[4];
#pragma unroll
    for (int p = 0; p < 4; p++) {
        const int n = wn * 64 + p * 16 + ((lane >> 4) & 1) * 8 + (lane & 7);
        b_row[p] = n * 128;
        b_sw[p]  = n & 7;
    }
    const uint32_t b_hc = (lane >> 3) & 1;

    float acc[2][8][4];
#pragma unroll
    for (int mt = 0; mt < 2; mt++)
#pragma unroll
        for (int nt = 0; nt < 8; nt++)
#pragma unroll
            for (int v = 0; v < 4; v++) acc[mt][nt][v] = 0.f;

    // prologue: NSTAGES-1 stages in flight
    load_stage(0);
    load_stage(1);

    for (int i = 0; i < KCHUNKS; i++) {
        CP_WAIT1();              // stage i arrived (2 groups pending -> <=1)
        __syncthreads();
        if (i + NSTAGES - 1 < KCHUNKS) load_stage(i + NSTAGES - 1);
        else CP_COMMIT();        // keep group count uniform for WAIT1

        const uint32_t st = tiles + (i % NSTAGES) * STAGE_B;
#pragma unroll
        for (int kk = 0; kk < 4; kk++) {
            uint32_t a[2][4];
#pragma unroll
            for (int mt = 0; mt < 2; mt++)
                ldsm4(a[mt], st + a_row[mt] +
                             (((2 * kk + a_hc) ^ a_sw[mt]) << 4));
            uint32_t b[4][4];
#pragma unroll
            for (int p = 0; p < 4; p++)
                ldsm4(b[p], st + 16384 + b_row[p] +
                            (((2 * kk + b_hc) ^ b_sw[p]) << 4));
#pragma unroll
            for (int mt = 0; mt < 2; mt++)
#pragma unroll
                for (int nt = 0; nt < 8; nt++)
                    mma_fp16(acc[mt][nt], a[mt],
                             b[nt >> 1][(nt & 1) * 2],
                             b[nt >> 1][(nt & 1) * 2 + 1]);
        }
    }

    // epilogue
    const int tg = lane >> 2;
    const int tc = (lane & 3) * 2;
#pragma unroll
    for (int mt = 0; mt < 2; mt++) {
#pragma unroll
        for (int h = 0; h < 2; h++) {
            const int m = wm * 32 + mt * 16 + h * 8 + tg;
            if (row0 + m < cnt) {
                const int   token = rows_s[m];
                const float g     = gates_s[m];
                float* orow = out + (size_t)token * D_HIDDEN + n0 + wn * 64;
#pragma unroll
                for (int nt = 0; nt < 8; nt++) {
                    float* p = orow + nt * 8 + tc;
                    float vx = g * acc[mt][nt][h * 2];
                    float vy = g * acc[mt][nt][h * 2 + 1];
                    if (SLOT == 1) {
                        float2 old = *(float2*)p;
                        vx += old.x; vy += old.y;
                    }
                    *(float2*)p = make_float2(vx, vy);
                }
            }
        }
    }
}

// ---------------- launch ----------------
extern "C" void kernel_launch(void* const* d_in, const int* in_sizes, int n_in,
                              void* d_out, int out_size) {
    (void)in_sizes; (void)n_in; (void)out_size;
    const float* x  = (const float*)d_in[0];
    const float* rw = (const float*)d_in[1];
    const float* ew = (const float*)d_in[2];
    float* out = (float*)d_out;

    cudaFuncSetAttribute(moe_gemm_mma<0>,
                         cudaFuncAttributeMaxDynamicSharedMemorySize, SMEM_DYN);
    cudaFuncSetAttribute(moe_gemm_mma<1>,
                         cudaFuncAttributeMaxDynamicSharedMemorySize, SMEM_DYN);

    reset_kernel<<<1, 32>>>();
    router_kernel<<<N_TOKENS, 128>>>(x, rw);
    convert_x_kernel<<<(N_TOKENS * D_MODEL / 4) / 256, 256>>>(x);
    convert_w_kernel<<<dim3(D_HIDDEN / 32, D_MODEL / 32, NUM_EXPERTS),
                       dim3(256)>>>(ew);

    dim3 grid(NTILES, N_TOKENS / BM, NUM_EXPERTS);  // (16, 64, 16), early-exit
    moe_gemm_mma<0><<<grid, 256, SMEM_DYN>>>(out);
    moe_gemm_mma<1><<<grid, 256, SMEM_DYN>>>(out);
}

// round 12
// speedup vs baseline: 1.0678x; 1.0678x over previous
#include <cuda_runtime.h>
#include <cuda_fp16.h>
#include <cstdint>

#define D_MODEL    2048
#define D_HIDDEN   2048
#define NUM_EXPERTS  16
#define N_TOKENS   8192

// mma.sync GEMM tile (round-10 best config)
#define BM 128
#define BN 128
#define BK 32
#define KCHUNKS (D_MODEL / BK)      // 64
#define NTILES  (D_HIDDEN / BN)     // 16
#define NSTAGES 4

// ---------------- device scratch (no allocations allowed) ----------------
__device__ int   g_counts[2][NUM_EXPERTS];
__device__ int   g_bucket[2][NUM_EXPERTS][N_TOKENS];
__device__ float g_gate  [2][NUM_EXPERTS][N_TOKENS];

__device__ __half g_xf[(size_t)N_TOKENS * D_MODEL];              // x -> fp16
// W transposed to [e][n][k] (K contiguous), rounded to fp16
__device__ __half g_wf[(size_t)NUM_EXPERTS * D_HIDDEN * D_MODEL];

// ---------------- PTX helpers (compute_103-safe: no tcgen05) ----------------
__device__ __forceinline__ uint32_t smem_u32(const void* p) {
    uint32_t a;
    asm("{ .reg .u64 t; cvta.to.shared.u64 t, %1; cvt.u32.u64 %0, t; }"
        : "=r"(a) : "l"(p));
    return a;
}
__device__ __forceinline__ void cp16(uint32_t dst, const void* src) {
    asm volatile("cp.async.cg.shared.global [%0], [%1], 16;\n"
                 :: "r"(dst), "l"(src));
}
#define CP_COMMIT() asm volatile("cp.async.commit_group;" ::: "memory")
#define CP_WAIT2()  asm volatile("cp.async.wait_group 2;" ::: "memory")

__device__ __forceinline__ void ldsm4(uint32_t* r, uint32_t addr) {
    asm volatile("ldmatrix.sync.aligned.m8n8.x4.shared.b16 {%0,%1,%2,%3}, [%4];"
                 : "=r"(r[0]), "=r"(r[1]), "=r"(r[2]), "=r"(r[3]) : "r"(addr));
}
__device__ __forceinline__ void mma_fp16(float* d, const uint32_t* a,
                                         uint32_t b0, uint32_t b1) {
    asm volatile(
        "mma.sync.aligned.m16n8k16.row.col.f32.f16.f16.f32 "
        "{%0,%1,%2,%3}, {%4,%5,%6,%7}, {%8,%9}, {%0,%1,%2,%3};"
        : "+f"(d[0]), "+f"(d[1]), "+f"(d[2]), "+f"(d[3])
        : "r"(a[0]), "r"(a[1]), "r"(a[2]), "r"(a[3]), "r"(b0), "r"(b1));
}

// ---------------- small kernels ----------------
__global__ void reset_kernel() {
    if (threadIdx.x < 2 * NUM_EXPERTS)
        ((int*)g_counts)[threadIdx.x] = 0;
}

// router + fused x->fp16 conversion (x row already staged in smem)
__global__ void router_kernel(const float* __restrict__ x,
                              const float* __restrict__ rw) {
    __shared__ float sx[D_MODEL];
    __shared__ float slog[NUM_EXPERTS];
    const int token = blockIdx.x;
    const int tid   = threadIdx.x;   // 128
    const float4* xr = (const float4*)(x + (size_t)token * D_MODEL);
    for (int i = tid; i < D_MODEL / 4; i += 128)
        ((float4*)sx)[i] = xr[i];
    __syncthreads();

    // emit fp16 copy of this row (from smem; no second global read of x)
    {
        __half2* dst = (__half2*)(g_xf + (size_t)token * D_MODEL);
#pragma unroll
        for (int i = tid; i < D_MODEL / 2; i += 128)
            dst[i] = __floats2half2_rn(sx[2 * i], sx[2 * i + 1]);
    }

    const int warp = tid >> 5, lane = tid & 31;
    for (int e = warp; e < NUM_EXPERTS; e += 4) {
        const float* w = rw + (size_t)e * D_MODEL;
        float s = 0.f;
#pragma unroll 8
        for (int i = lane; i < D_MODEL; i += 32)
            s += sx[i] * __ldg(w + i);
#pragma unroll
        for (int o = 16; o > 0; o >>= 1)
            s += __shfl_xor_sync(0xffffffffu, s, o);
        if (lane == 0) slog[e] = s;
    }
    __syncthreads();

    if (tid == 0) {
        float l0 = -3.4e38f, l1 = -3.4e38f;
        int e0 = 0, e1 = 0;
#pragma unroll
        for (int e = 0; e < NUM_EXPERTS; e++) {
            float v = slog[e];
            if (v > l0)      { l1 = l0; e1 = e0; l0 = v; e0 = e; }
            else if (v > l1) { l1 = v;  e1 = e; }
        }
        float g0 = 1.f / (1.f + expf(l1 - l0));
        float g1 = 1.f - g0;
        int p0 = atomicAdd(&g_counts[0][e0], 1);
        g_bucket[0][e0][p0] = token;
        g_gate  [0][e0][p0] = g0;
        int p1 = atomicAdd(&g_counts[1][e1], 1);
        g_bucket[1][e1][p1] = token;
        g_gate  [1][e1][p1] = g1;
    }
}

// W [e][k][n] fp32 -> transposed fp16 [e][n][k]; 32(k) x 128(n) tile per block
__global__ void convert_w_kernel(const float* __restrict__ W) {
    __shared__ float t[32][129];        // [k][n], pad -> conflict-free
    const int e  = blockIdx.z;
    const int k0 = blockIdx.y * 32;
    const int n0 = blockIdx.x * 128;
    const int tid = threadIdx.x;        // 256
    const float* src = W + (size_t)e * D_MODEL * D_HIDDEN;

    // read 32x128 fp32 tile: 1024 float4, 4 per thread (MLP 4)
#pragma unroll
    for (int it = 0; it < 4; it++) {
        const int idx = it * 256 + tid;
        const int r  = idx >> 5;        // 0..31 (k)
        const int c4 = idx & 31;        // 0..31 (n group of 4)
        float4 v = *(const float4*)&src[(size_t)(k0 + r) * D_HIDDEN + n0 + c4 * 4];
        t[r][c4 * 4 + 0] = v.x;
        t[r][c4 * 4 + 1] = v.y;
        t[r][c4 * 4 + 2] = v.z;
        t[r][c4 * 4 + 3] = v.w;
    }
    __syncthreads();

    // write 128(n) x 32(k) fp16: 1024 x 8B stores, 4 per thread
#pragma unroll
    for (int it = 0; it < 4; it++) {
        const int idx = it * 256 + tid;
        const int n  = idx >> 3;        // 0..127
        const int kg = idx & 7;         // 0..7 -> k = kg*4..+3
        float f[4];
#pragma unroll
        for (int j = 0; j < 4; j++) f[j] = t[kg * 4 + j][n];
        __half2 p0 = __floats2half2_rn(f[0], f[1]);
        __half2 p1 = __floats2half2_rn(f[2], f[3]);
        size_t o = ((size_t)e * D_HIDDEN + n0 + n) * D_MODEL + k0 + kg * 4;
        *(__half2*)&g_wf[o]     = p0;
        *(__half2*)&g_wf[o + 2] = p1;
    }
}

// ---------------- mma.sync gathered GEMM (fp16, 8 warps, 4-stage pipe) ------
// smem: [0:512) rows_s | [512:1024) gates_s | [1024:) 4 stages x 16KB
//   stage: A 8K | B 8K   (tiles 128 rows x 32 fp16,
//   row = 64B = 4 x 16B chunks, chunk swizzle c' = c ^ ((row>>1)&3))
#define STAGE_B  16384
#define SMEM_DYN (1024 + NSTAGES * STAGE_B)

template <int SLOT>
__global__ void __launch_bounds__(256, 2)
moe_gemm_mma(float* __restrict__ out) {
    const int e    = blockIdx.z;
    const int cnt  = g_counts[SLOT][e];
    const int row0 = blockIdx.y * BM;
    if (row0 >= cnt) return;
    const int n0  = blockIdx.x * BN;
    const int tid = threadIdx.x;

    extern __shared__ char smem[];
    int*   rows_s  = (int*)smem;
    float* gates_s = (float*)(smem + 512);
    const uint32_t sb    = smem_u32(smem);
    const uint32_t tiles = sb + 1024;

    if (tid < BM) {
        int idx = row0 + tid;
        if (idx < cnt) {
            rows_s[tid]  = g_bucket[SLOT][e][idx];
            gates_s[tid] = g_gate[SLOT][e][idx];
        } else {
            rows_s[tid]  = g_bucket[SLOT][e][row0];
            gates_s[tid] = 0.f;
        }
    }
    __syncthreads();

    const size_t wbase = ((size_t)e * D_HIDDEN + n0) * D_MODEL;

    // stage loader: 2 x 512 16B chunks, 2 chunk-slots per thread
    auto load_stage = [&](int i) {
        const int kof = i * BK;
        const uint32_t st = tiles + (i & (NSTAGES - 1)) * STAGE_B;
#pragma unroll
        for (int q = 0; q < 2; q++) {
            const int ch = tid * 2 + q;
            const int r = ch >> 2, c = ch & 3;
            const uint32_t d = r * 64 + ((c ^ ((r >> 1) & 3)) << 4);
            const size_t asrc = (size_t)rows_s[r] * D_MODEL + kof + c * 8;
            cp16(st + d, g_xf + asrc);
            const size_t bsrc = wbase + (size_t)r * D_MODEL + kof + c * 8;
            cp16(st + 8192 + d, g_wf + bsrc);
        }
        CP_COMMIT();
    };

    // warp layout: 4 (M) x 2 (N); warp tile 32x64
    const int wid = tid >> 5, lane = tid & 31;
    const int wm = wid & 3, wn = wid >> 2;

    // per-lane ldmatrix address components
    uint32_t a_row[2], a_sw[2];
#pragma unroll
    for (int mt = 0; mt < 2; mt++) {
        const int m = wm * 32 + mt * 16 + ((lane >> 3) & 1) * 8 + (lane & 7);
        a_row[mt] = m * 64;
        a_sw[mt]  = (m >> 1) & 3;
    }
    const uint32_t a_hc = lane >> 4;
    uint32_t b_row[4], b_sw[4];
#pragma unroll
    for (int p = 0; p < 4; p++) {
        const int n = wn * 64 + p * 16 + ((lane >> 4) & 1) * 8 + (lane & 7);
        b_row[p] = n * 64;
        b_sw[p]  = (n >> 1) & 3;
    }
    const uint32_t b_hc = (lane >> 3) & 1;

    float acc[2][8][4];
#pragma unroll
    for (int mt = 0; mt < 2; mt++)
#pragma unroll
        for (int nt = 0; nt < 8; nt++)
#pragma unroll
            for (int v = 0; v < 4; v++) acc[mt][nt][v] = 0.f;

    // prologue: NSTAGES-1 stages in flight
    load_stage(0);
    load_stage(1);
    load_stage(2);

    for (int i = 0; i < KCHUNKS; i++) {
        CP_WAIT2();              // stage i arrived (3 groups pending -> <=2)
        __syncthreads();
        if (i + NSTAGES - 1 < KCHUNKS) load_stage(i + NSTAGES - 1);
        else CP_COMMIT();        // keep group count uniform for WAIT2

        const uint32_t st = tiles + (i & (NSTAGES - 1)) * STAGE_B;
#pragma unroll
        for (int kk = 0; kk < 2; kk++) {
            uint32_t a[2][4];
#pragma unroll
            for (int mt = 0; mt < 2; mt++)
                ldsm4(a[mt], st + a_row[mt] +
                             (((2 * kk + a_hc) ^ a_sw[mt]) << 4));
            uint32_t b[4][4];
#pragma unroll
            for (int p = 0; p < 4; p++)
                ldsm4(b[p], st + 8192 + b_row[p] +
                            (((2 * kk + b_hc) ^ b_sw[p]) << 4));
#pragma unroll
            for (int mt = 0; mt < 2; mt++)
#pragma unroll
                for (int nt = 0; nt < 8; nt++)
                    mma_fp16(acc[mt][nt], a[mt],
                             b[nt >> 1][(nt & 1) * 2],
                             b[nt >> 1][(nt & 1) * 2 + 1]);
        }
    }

    // epilogue
    const int tg = lane >> 2;
    const int tc = (lane & 3) * 2;
#pragma unroll
    for (int mt = 0; mt < 2; mt++) {
#pragma unroll
        for (int h = 0; h < 2; h++) {
            const int m = wm * 32 + mt * 16 + h * 8 + tg;
            if (row0 + m < cnt) {
                const int   token = rows_s[m];
                const float g     = gates_s[m];
                float* orow = out + (size_t)token * D_HIDDEN + n0 + wn * 64;
#pragma unroll
                for (int nt = 0; nt < 8; nt++) {
                    float* p = orow + nt * 8 + tc;
                    float vx = g * acc[mt][nt][h * 2];
                    float vy = g * acc[mt][nt][h * 2 + 1];
                    if (SLOT == 1) {
                        float2 old = *(float2*)p;
                        vx += old.x; vy += old.y;
                    }
                    *(float2*)p = make_float2(vx, vy);
                }
            }
        }
    }
}

// ---------------- launch ----------------
extern "C" void kernel_launch(void* const* d_in, const int* in_sizes, int n_in,
                              void* d_out, int out_size) {
    (void)in_sizes; (void)n_in; (void)out_size;
    const float* x  = (const float*)d_in[0];
    const float* rw = (const float*)d_in[1];
    const float* ew = (const float*)d_in[2];
    float* out = (float*)d_out;

    cudaFuncSetAttribute(moe_gemm_mma<0>,
                         cudaFuncAttributeMaxDynamicSharedMemorySize, SMEM_DYN);
    cudaFuncSetAttribute(moe_gemm_mma<1>,
                         cudaFuncAttributeMaxDynamicSharedMemorySize, SMEM_DYN);

    reset_kernel<<<1, 32>>>();
    router_kernel<<<N_TOKENS, 128>>>(x, rw);
    convert_w_kernel<<<dim3(D_HIDDEN / 128, D_MODEL / 32, NUM_EXPERTS),
                       dim3(256)>>>(ew);

    dim3 grid(NTILES, N_TOKENS / BM, NUM_EXPERTS);  // (16, 64, 16), early-exit
    moe_gemm_mma<0><<<grid, 256, SMEM_DYN>>>(out);
    moe_gemm_mma<1><<<grid, 256, SMEM_DYN>>>(out);
}